// round 1
// baseline (speedup 1.0000x reference)
#include <cuda_runtime.h>

// y = s1 * FWHT( g * FWHT( s2 * x ) ) per token, D = 4096.
// FWHT decomposition per token (256 threads):
//   layout L0: v[r] = x[t + 256*r]         (r = bits 8..11, lane = bits 0..4, warp = bits 5..7)
//   FWHT1: reg stages bits 8..11, shuffle stages bits 0..4, smem exchange -> L1, reg stages bits 5..7
//   layout L1: u[p][k] = idx l + (k<<5) + ((2w+p)<<8)
//   FWHT2: reg stages bits 5..7, reg stage bit 8 (p), shuffle stages bits 0..4,
//          smem exchange -> L2, reg stages bits 9..11
//   layout L2: z[p][j] = idx t + (p<<8) + (j<<9)

#define DDIM 4096
#define TPC  4      // tokens per CTA

__device__ __forceinline__ float softplus_f(float x) {
    // numerically stable log(1 + e^x), matches jax.nn.softplus
    return fmaxf(x, 0.0f) + log1pf(expf(-fabsf(x)));
}

__global__ void __launch_bounds__(256)
whvi_kernel(const float* __restrict__ x,
            const float* __restrict__ s1,
            const float* __restrict__ s2,
            const float* __restrict__ g_mu,
            const float* __restrict__ g_rho,
            const float* __restrict__ eps,
            float* __restrict__ out,
            int n_tokens)
{
    __shared__ float sh[DDIM];

    const int t = threadIdx.x;       // 0..255
    const int l = t & 31;            // lane   = bits 0..4 of index
    const int w = t >> 5;            // warp   = bits 5..7 of index

    // ---- per-CTA parameter preload (registers) ----
    float sp2[16];
#pragma unroll
    for (int r = 0; r < 16; r++) sp2[r] = s2[t + 256 * r];

    float gg[2][8];
#pragma unroll
    for (int p = 0; p < 2; p++)
#pragma unroll
        for (int k = 0; k < 8; k++) {
            int i = l + (k << 5) + (((w << 1) + p) << 8);
            gg[p][k] = g_mu[i] + softplus_f(g_rho[i]) * eps[i];
        }

    float sp1[2][8];
#pragma unroll
    for (int p = 0; p < 2; p++)
#pragma unroll
        for (int j = 0; j < 8; j++)
            sp1[p][j] = s1[t + (p << 8) + (j << 9)];

    const int tok0 = blockIdx.x * TPC;

    for (int it = 0; it < TPC; it++) {
        const int tok = tok0 + it;
        if (tok >= n_tokens) break;
        const float* __restrict__ xr = x + (size_t)tok * DDIM;

        // ---- load + scale by s2 (L0 layout) ----
        float v[16];
#pragma unroll
        for (int r = 0; r < 16; r++)
            v[r] = xr[t + 256 * r] * sp2[r];

        // ---- FWHT1: register stages, bits 8..11 (r dimension) ----
#pragma unroll
        for (int b = 0; b < 4; b++) {
            const int m = 1 << b;
#pragma unroll
            for (int r = 0; r < 16; r++) {
                if (!(r & m)) {
                    float a = v[r], c = v[r | m];
                    v[r]     = a + c;
                    v[r | m] = a - c;
                }
            }
        }

        // ---- FWHT1: shuffle stages, bits 0..4 (lane dimension) ----
#pragma unroll
        for (int s = 0; s < 5; s++) {
            const int m = 1 << s;
            const float sgn = (l & m) ? -1.0f : 1.0f;
#pragma unroll
            for (int r = 0; r < 16; r++) {
                float pv = __shfl_xor_sync(0xffffffffu, v[r], m);
                v[r] = fmaf(sgn, v[r], pv);
            }
        }

        // ---- exchange 1 (conflict-free): L0 -> L1 ----
        __syncthreads();              // guard previous iteration's reads of sh
#pragma unroll
        for (int r = 0; r < 16; r++)
            sh[t + 256 * r] = v[r];
        __syncthreads();

        float u[2][8];
#pragma unroll
        for (int p = 0; p < 2; p++)
#pragma unroll
            for (int k = 0; k < 8; k++)
                u[p][k] = sh[l + (k << 5) + (((w << 1) + p) << 8)];

        // ---- FWHT1: register stages, bits 5..7 (k dimension) ----
#pragma unroll
        for (int b = 0; b < 3; b++) {
            const int m = 1 << b;
#pragma unroll
            for (int p = 0; p < 2; p++)
#pragma unroll
                for (int k = 0; k < 8; k++) {
                    if (!(k & m)) {
                        float a = u[p][k], c = u[p][k | m];
                        u[p][k]     = a + c;
                        u[p][k | m] = a - c;
                    }
                }
        }

        // ---- elementwise multiply by g_tilde ----
#pragma unroll
        for (int p = 0; p < 2; p++)
#pragma unroll
            for (int k = 0; k < 8; k++)
                u[p][k] *= gg[p][k];

        // ---- FWHT2: register stages, bits 5..7 (k dimension) ----
#pragma unroll
        for (int b = 0; b < 3; b++) {
            const int m = 1 << b;
#pragma unroll
            for (int p = 0; p < 2; p++)
#pragma unroll
                for (int k = 0; k < 8; k++) {
                    if (!(k & m)) {
                        float a = u[p][k], c = u[p][k | m];
                        u[p][k]     = a + c;
                        u[p][k | m] = a - c;
                    }
                }
        }

        // ---- FWHT2: register stage, bit 8 (p dimension) ----
#pragma unroll
        for (int k = 0; k < 8; k++) {
            float a = u[0][k], c = u[1][k];
            u[0][k] = a + c;
            u[1][k] = a - c;
        }

        // ---- FWHT2: shuffle stages, bits 0..4 ----
#pragma unroll
        for (int s = 0; s < 5; s++) {
            const int m = 1 << s;
            const float sgn = (l & m) ? -1.0f : 1.0f;
#pragma unroll
            for (int p = 0; p < 2; p++)
#pragma unroll
                for (int k = 0; k < 8; k++) {
                    float pv = __shfl_xor_sync(0xffffffffu, u[p][k], m);
                    u[p][k] = fmaf(sgn, u[p][k], pv);
                }
        }

        // ---- exchange 2 (conflict-free): L1 -> L2 ----
        __syncthreads();              // guard exchange-1 reads
#pragma unroll
        for (int p = 0; p < 2; p++)
#pragma unroll
            for (int k = 0; k < 8; k++)
                sh[l + (k << 5) + (((w << 1) + p) << 8)] = u[p][k];
        __syncthreads();

        float z[2][8];
#pragma unroll
        for (int p = 0; p < 2; p++)
#pragma unroll
            for (int j = 0; j < 8; j++)
                z[p][j] = sh[t + (p << 8) + (j << 9)];

        // ---- FWHT2: register stages, bits 9..11 (j dimension) ----
#pragma unroll
        for (int b = 0; b < 3; b++) {
            const int m = 1 << b;
#pragma unroll
            for (int p = 0; p < 2; p++)
#pragma unroll
                for (int j = 0; j < 8; j++) {
                    if (!(j & m)) {
                        float a = z[p][j], c = z[p][j | m];
                        z[p][j]     = a + c;
                        z[p][j | m] = a - c;
                    }
                }
        }

        // ---- scale by s1 and store (coalesced) ----
        float* __restrict__ orow = out + (size_t)tok * DDIM;
#pragma unroll
        for (int p = 0; p < 2; p++)
#pragma unroll
            for (int j = 0; j < 8; j++)
                orow[t + (p << 8) + (j << 9)] = z[p][j] * sp1[p][j];
    }
}

extern "C" void kernel_launch(void* const* d_in, const int* in_sizes, int n_in,
                              void* d_out, int out_size)
{
    const float* x     = (const float*)d_in[0];
    const float* s1    = (const float*)d_in[1];
    const float* s2    = (const float*)d_in[2];
    const float* g_mu  = (const float*)d_in[3];
    const float* g_rho = (const float*)d_in[4];
    const float* eps   = (const float*)d_in[5];
    // d_in[6] = H, unused (FWHT computes it implicitly)

    float* out = (float*)d_out;
    const int n_tokens = in_sizes[0] / DDIM;
    const int grid = (n_tokens + TPC - 1) / TPC;

    whvi_kernel<<<grid, 256>>>(x, s1, s2, g_mu, g_rho, eps, out, n_tokens);
}